// round 5
// baseline (speedup 1.0000x reference)
#include <cuda_runtime.h>
#include <cstdint>

#define LMAX  6
#define BATCH 1024
#define F     64
#define IR    455
#define NROT  64
#define FS    (F * IR)   // 29120 floats per batch element

// Packed, pre-scaled weight matrices W_l[k, n], k=(f*d+u), n=(g*d+v), row-major KxN.
__device__ float g_W[4096 * 455];

// Tile decode tables, ordered l = 6..0 (largest K first).
__constant__ int c_cnt[7]  = {1352, 968, 648, 392, 200, 72, 8}; // 8*d*d
__constant__ int c_d[7]    = {13, 11, 9, 7, 5, 3, 1};
__constant__ int c_off[7]  = {286, 165, 84, 35, 10, 1, 0};

// ---------------------------------------------------------------------------
// Kernel 1: W_l[(f*d+u), (g*d+v)] = scale_l * sum_r D[r, off + u*d + v] * w[f,g,r]
// ---------------------------------------------------------------------------
__global__ void __launch_bounds__(256) build_w_kernel(const float* __restrict__ D,
                                                      const float* __restrict__ w)
{
    const int dtab[7] = {1, 3, 5, 7, 9, 11, 13};
    const int otab[7] = {0, 1, 10, 35, 84, 165, 286};

    const int l   = blockIdx.x;
    const int f   = blockIdx.y;
    const int d   = dtab[l];
    const int off = otab[l];
    const int d2  = d * d;
    const int N   = 64 * d;
    const int Woff = 4096 * otab[l];
    const float scale = rsqrtf((float)d) * (1.0f / 64.0f);

    __shared__ float Dsh[64 * 169];

    for (int idx = threadIdx.x; idx < 64 * d2; idx += blockDim.x) {
        int r = idx / d2;
        int j = idx - r * d2;
        Dsh[r * d2 + j] = D[r * IR + off + j];
    }
    __syncthreads();

    const float* wf = w + f * 64 * 64;

    for (int e = threadIdx.x; e < 64 * d2; e += blockDim.x) {
        int u   = e / (64 * d);
        int rem = e - u * 64 * d;
        int g   = rem / d;
        int v   = rem - g * d;

        const float* wr = wf + g * 64;
        const int dj = u * d + v;

        float acc = 0.0f;
#pragma unroll 8
        for (int r = 0; r < 64; ++r)
            acc += Dsh[r * d2 + dj] * wr[r];

        g_W[Woff + (f * d + u) * N + g * d + v] = scale * acc;
    }
}

// ---------------------------------------------------------------------------
// helpers
// ---------------------------------------------------------------------------
__device__ __forceinline__ float f2tf32(float x) {
    uint32_t r;
    asm("cvt.rna.tf32.f32 %0, %1;" : "=r"(r) : "f"(x));
    return __uint_as_float(r);
}

__device__ __forceinline__ void mma_tf32(float c[4],
                                         const uint32_t a[4],
                                         const uint32_t b[2])
{
    asm volatile(
        "mma.sync.aligned.m16n8k8.row.col.f32.tf32.tf32.f32 "
        "{%0,%1,%2,%3}, {%4,%5,%6,%7}, {%8,%9}, {%0,%1,%2,%3};"
        : "+f"(c[0]), "+f"(c[1]), "+f"(c[2]), "+f"(c[3])
        : "r"(a[0]), "r"(a[1]), "r"(a[2]), "r"(a[3]), "r"(b[0]), "r"(b[1]));
}

__device__ __forceinline__ void cp4(uint32_t s, const float* g) {
    asm volatile("cp.async.ca.shared.global [%0], [%1], 4;" :: "r"(s), "l"(g));
}
__device__ __forceinline__ void cp16(uint32_t s, const float* g) {
    asm volatile("cp.async.cg.shared.global [%0], [%1], 16;" :: "r"(s), "l"(g));
}
__device__ __forceinline__ void cp_commit() {
    asm volatile("cp.async.commit_group;");
}
template <int W>
__device__ __forceinline__ void cp_wait() {
    asm volatile("cp.async.wait_group %0;" :: "n"(W));
}

// ---------------------------------------------------------------------------
// Fused GEMM over all l. One block = one 128x64 C tile of one l.
// 2-stage cp.async pipeline, raw f32 in smem, 3xTF32 split at fragment load.
// ---------------------------------------------------------------------------
__global__ void __launch_bounds__(256) so3_fused_kernel(const float* __restrict__ x,
                                                        float* __restrict__ out)
{
    // ---- decode (l, bm, bn) from blockIdx.x ----
    int rem = blockIdx.x;
    int idx = 0;
#pragma unroll
    for (int j = 0; j < 6; ++j)
        if (rem >= c_cnt[idx]) { rem -= c_cnt[idx]; idx++; }
    const int d    = c_d[idx];
    const int off  = c_off[idx];
    const int Woff = 4096 * c_off[idx];
    const int bn   = rem % d;
    const int bm   = rem / d;

    const int N = 64 * d;
    const int K = 64 * d;

    __shared__ __align__(16) float As[2][16][132];
    __shared__ __align__(16) float Bs[2][16][68];

    const int t    = threadIdx.x;
    const int wid  = t >> 5;
    const int lane = t & 31;
    const int g    = lane >> 2;        // 0..7
    const int tg   = lane & 3;         // 0..3
    const int wm   = (wid & 3) * 32;   // warp m-offset
    const int wn   = (wid >> 2) * 32;  // warp n-offset

    // ---- A staging mapping: row lrA, k-range [kcA8, kcA8+8) ----
    const int lrA  = t & 127;
    const int kcA8 = (t >> 7) * 8;     // 0 or 8
    const int growA = bm * 128 + lrA;
    const int bA = growA / d;
    const int mA = growA - bA * d;
    const float* xb = x + bA * FS + off + mA;

    // incremental (f,u) decomposition of k = kt + kcA8
    int fb = kcA8 / d;
    int ub = kcA8 - fb * d;
    const int q16 = 16 / d;
    const int r16 = 16 - q16 * d;

    // ---- B staging mapping: 16B per thread ----
    const int klB = t >> 4;            // 0..15
    const int c4  = (t & 15) * 4;      // 0..60
    const float* Wp = g_W + Woff + klB * N + bn * 64 + c4;

    // smem byte addresses
    const uint32_t as_base = (uint32_t)__cvta_generic_to_shared(&As[0][0][0]);
    const uint32_t bs_base = (uint32_t)__cvta_generic_to_shared(&Bs[0][0][0]);
    const uint32_t as_stage = 16 * 132 * 4;
    const uint32_t bs_stage = 16 * 68 * 4;
    const uint32_t asA = as_base + (kcA8 * 132 + lrA) * 4;
    const uint32_t bsB = bs_base + (klB * 68 + c4) * 4;

    float acc[2][4][4] = {};

    // ---- prologue: stage tile 0 ----
    {
        int f = fb, u = ub;
#pragma unroll
        for (int i = 0; i < 8; ++i) {
            cp4(asA + i * (132 * 4), xb + f * IR + u * d);
            if (++u == d) { u = 0; f++; }
        }
        cp16(bsB, Wp);
        cp_commit();
        fb += q16; ub += r16; if (ub >= d) { ub -= d; fb++; }
        Wp += 16 * N;
    }

    const int ntiles = K >> 4;
    for (int it = 0; it < ntiles; ++it) {
        const int s = it & 1;

        // issue next stage
        if (it + 1 < ntiles) {
            const uint32_t so = (s ^ 1) ? 1u : 0u;
            int f = fb, u = ub;
#pragma unroll
            for (int i = 0; i < 8; ++i) {
                cp4(asA + so * as_stage + i * (132 * 4), xb + f * IR + u * d);
                if (++u == d) { u = 0; f++; }
            }
            cp16(bsB + so * bs_stage, Wp);
            cp_commit();
            fb += q16; ub += r16; if (ub >= d) { ub -= d; fb++; }
            Wp += 16 * N;
            cp_wait<1>();
        } else {
            cp_wait<0>();
        }
        __syncthreads();

        // ---- compute on stage s ----
#pragma unroll
        for (int ks = 0; ks < 16; ks += 8) {
            uint32_t ah[2][4], al[2][4], bh[4][2], bl[4][2];
#pragma unroll
            for (int mi = 0; mi < 2; ++mi) {
                const int mb = wm + mi * 16 + g;
                float r0 = As[s][ks + tg    ][mb    ];
                float r1 = As[s][ks + tg    ][mb + 8];
                float r2 = As[s][ks + tg + 4][mb    ];
                float r3 = As[s][ks + tg + 4][mb + 8];
                float h0 = f2tf32(r0), h1 = f2tf32(r1), h2 = f2tf32(r2), h3 = f2tf32(r3);
                ah[mi][0] = __float_as_uint(h0);
                ah[mi][1] = __float_as_uint(h1);
                ah[mi][2] = __float_as_uint(h2);
                ah[mi][3] = __float_as_uint(h3);
                al[mi][0] = __float_as_uint(f2tf32(r0 - h0));
                al[mi][1] = __float_as_uint(f2tf32(r1 - h1));
                al[mi][2] = __float_as_uint(f2tf32(r2 - h2));
                al[mi][3] = __float_as_uint(f2tf32(r3 - h3));
            }
#pragma unroll
            for (int ni = 0; ni < 4; ++ni) {
                const int nb = wn + ni * 8 + g;
                float r0 = Bs[s][ks + tg    ][nb];
                float r1 = Bs[s][ks + tg + 4][nb];
                float h0 = f2tf32(r0), h1 = f2tf32(r1);
                bh[ni][0] = __float_as_uint(h0);
                bh[ni][1] = __float_as_uint(h1);
                bl[ni][0] = __float_as_uint(f2tf32(r0 - h0));
                bl[ni][1] = __float_as_uint(f2tf32(r1 - h1));
            }
#pragma unroll
            for (int mi = 0; mi < 2; ++mi)
#pragma unroll
                for (int ni = 0; ni < 4; ++ni) {
                    mma_tf32(acc[mi][ni], ah[mi], bh[ni]);   // hi*hi
                    mma_tf32(acc[mi][ni], ah[mi], bl[ni]);   // hi*lo
                    mma_tf32(acc[mi][ni], al[mi], bh[ni]);   // lo*hi
                }
        }
        __syncthreads();
    }

    // ---- epilogue: scatter into out[b, g, off + v*d + m] ----
#pragma unroll
    for (int mi = 0; mi < 2; ++mi) {
#pragma unroll
        for (int cr = 0; cr < 2; ++cr) {
            const int row = bm * 128 + wm + mi * 16 + g + cr * 8;
            const int b = row / d;
            const int m = row - b * d;
            float* ob = out + b * FS + off + m;
#pragma unroll
            for (int ni = 0; ni < 4; ++ni) {
#pragma unroll
                for (int cc = 0; cc < 2; ++cc) {
                    const int col = bn * 64 + wn + ni * 8 + tg * 2 + cc;
                    const int gg = col / d;
                    const int v  = col - gg * d;
                    ob[gg * IR + v * d] = acc[mi][ni][cr * 2 + cc];
                }
            }
        }
    }
}

// ---------------------------------------------------------------------------
extern "C" void kernel_launch(void* const* d_in, const int* in_sizes, int n_in,
                              void* d_out, int out_size)
{
    const float* x = nullptr;
    const float* D = nullptr;
    const float* w = nullptr;
    for (int i = 0; i < n_in; ++i) {
        if (in_sizes[i] == NROT * IR)         D = (const float*)d_in[i];
        else if (in_sizes[i] == F * F * NROT) w = (const float*)d_in[i];
        else                                  x = (const float*)d_in[i];
    }
    float* out = (float*)d_out;

    build_w_kernel<<<dim3(LMAX + 1, F), 256>>>(D, w);

    // Total tiles: sum over l of (8d)*(d) = 8 * 455 = 3640
    so3_fused_kernel<<<3640, 256>>>(x, out);
}

// round 6
// speedup vs baseline: 1.3704x; 1.3704x over previous
#include <cuda_runtime.h>
#include <cstdint>

#define LMAX  6
#define BATCH 1024
#define F     64
#define IR    455
#define NROT  64
#define FS    (F * IR)   // 29120 floats per batch element

// Raw packed pre-scaled weights W_l[k, n] (f32), k=(f*d+u), n=(g*d+v).
__device__ float g_W[4096 * 455];
// bf16x2-packed (along k) hi/lo planes of W: element (k2, n) packs k=2k2 (lo16), 2k2+1 (hi16).
__device__ uint32_t g_Wp_hi[2048 * 455];
__device__ uint32_t g_Wp_lo[2048 * 455];

// Tile decode tables, ordered l = 6..0 (largest K first).
__constant__ int c_cnt[7]  = {1352, 968, 648, 392, 200, 72, 8}; // 8*d*d
__constant__ int c_d[7]    = {13, 11, 9, 7, 5, 3, 1};
__constant__ int c_off[7]  = {286, 165, 84, 35, 10, 1, 0};

// ---------------------------------------------------------------------------
// Kernel 1: W_l[(f*d+u), (g*d+v)] = scale_l * sum_r D[r, off + u*d + v] * w[f,g,r]
// ---------------------------------------------------------------------------
__global__ void __launch_bounds__(256) build_w_kernel(const float* __restrict__ D,
                                                      const float* __restrict__ w)
{
    const int dtab[7] = {1, 3, 5, 7, 9, 11, 13};
    const int otab[7] = {0, 1, 10, 35, 84, 165, 286};

    const int l   = blockIdx.x;
    const int f   = blockIdx.y;
    const int d   = dtab[l];
    const int off = otab[l];
    const int d2  = d * d;
    const int N   = 64 * d;
    const int Woff = 4096 * otab[l];
    const float scale = rsqrtf((float)d) * (1.0f / 64.0f);

    __shared__ float Dsh[64 * 169];

    for (int idx = threadIdx.x; idx < 64 * d2; idx += blockDim.x) {
        int r = idx / d2;
        int j = idx - r * d2;
        Dsh[r * d2 + j] = D[r * IR + off + j];
    }
    __syncthreads();

    const float* wf = w + f * 64 * 64;

    for (int e = threadIdx.x; e < 64 * d2; e += blockDim.x) {
        int u   = e / (64 * d);
        int rem = e - u * 64 * d;
        int g   = rem / d;
        int v   = rem - g * d;

        const float* wr = wf + g * 64;
        const int dj = u * d + v;

        float acc = 0.0f;
#pragma unroll 8
        for (int r = 0; r < 64; ++r)
            acc += Dsh[r * d2 + dj] * wr[r];

        g_W[Woff + (f * d + u) * N + g * d + v] = scale * acc;
    }
}

// ---------------------------------------------------------------------------
// bf16 helpers
// ---------------------------------------------------------------------------
__device__ __forceinline__ uint32_t pack_bf16x2(float lo_e, float hi_e) {
    uint32_t r;
    asm("cvt.rn.bf16x2.f32 %0, %1, %2;" : "=r"(r) : "f"(hi_e), "f"(lo_e));
    return r;
}
__device__ __forceinline__ float bf16_lo_f32(uint32_t p) { return __uint_as_float(p << 16); }
__device__ __forceinline__ float bf16_hi_f32(uint32_t p) { return __uint_as_float(p & 0xffff0000u); }

__device__ __forceinline__ uint32_t split_pack(float e0, float e1, uint32_t& lo_out) {
    uint32_t hi = pack_bf16x2(e0, e1);
    lo_out = pack_bf16x2(e0 - bf16_lo_f32(hi), e1 - bf16_hi_f32(hi));
    return hi;
}

__device__ __forceinline__ void mma_bf16(float c[4],
                                         const uint32_t a[4],
                                         const uint32_t b[2])
{
    asm volatile(
        "mma.sync.aligned.m16n8k16.row.col.f32.bf16.bf16.f32 "
        "{%0,%1,%2,%3}, {%4,%5,%6,%7}, {%8,%9}, {%0,%1,%2,%3};"
        : "+f"(c[0]), "+f"(c[1]), "+f"(c[2]), "+f"(c[3])
        : "r"(a[0]), "r"(a[1]), "r"(a[2]), "r"(a[3]), "r"(b[0]), "r"(b[1]));
}

__device__ __forceinline__ void cp4(uint32_t s, const float* g) {
    asm volatile("cp.async.ca.shared.global [%0], [%1], 4;" :: "r"(s), "l"(g));
}
__device__ __forceinline__ void cp16(uint32_t s, const void* g) {
    asm volatile("cp.async.cg.shared.global [%0], [%1], 16;" :: "r"(s), "l"(g));
}
__device__ __forceinline__ void cp_commit() {
    asm volatile("cp.async.commit_group;");
}
template <int W>
__device__ __forceinline__ void cp_wait() {
    asm volatile("cp.async.wait_group %0;" :: "n"(W));
}

// ---------------------------------------------------------------------------
// Kernel 1b: pack g_W into bf16x2 hi/lo planes, pairs along k.
// grid = (1352, 7): blockIdx.y = l (index into big-first tables not needed; use dtab order)
// ---------------------------------------------------------------------------
__global__ void __launch_bounds__(256) pack_w_kernel()
{
    const int dtab[7] = {1, 3, 5, 7, 9, 11, 13};
    const int otab[7] = {0, 1, 10, 35, 84, 165, 286};

    const int l = blockIdx.y;
    const int d = dtab[l];
    const int N = 64 * d;
    const int tot = 2048 * d * d;     // (32d) * (64d)
    const int idx = blockIdx.x * 256 + threadIdx.x;
    if (idx >= tot) return;

    const int k2 = idx / N;
    const int n  = idx - k2 * N;
    const int rbase = 4096 * otab[l];

    float e0 = g_W[rbase + (2 * k2) * N + n];
    float e1 = g_W[rbase + (2 * k2 + 1) * N + n];
    uint32_t lo;
    uint32_t hi = split_pack(e0, e1, lo);
    g_Wp_hi[2048 * otab[l] + idx] = hi;
    g_Wp_lo[2048 * otab[l] + idx] = lo;
}

// ---------------------------------------------------------------------------
// Kernel 2: fused GEMM, bf16x2-split tensor cores.
//   C[(b,m),(g,v)] = sum_k A * W ; block tile 128x64, BK=16 (one k16 MMA step/tile).
//   2-stage cp.async for raw A (f32 gather) and pre-split B planes.
//   Per-tile convert phase packs A into bf16x2 hi/lo planes.
// ---------------------------------------------------------------------------
__global__ void __launch_bounds__(256) so3_bf16_kernel(const float* __restrict__ x,
                                                       float* __restrict__ out)
{
    // ---- decode (l, bm, bn) ----
    int rem = blockIdx.x;
    int li = 0;
#pragma unroll
    for (int j = 0; j < 6; ++j)
        if (rem >= c_cnt[li]) { rem -= c_cnt[li]; li++; }
    const int d    = c_d[li];
    const int offl = c_off[li];
    const int bn   = rem % d;
    const int bm   = rem / d;

    const int N = 64 * d;
    const int K = 64 * d;

    __shared__ __align__(16) float    Araw[2][16 * 128];
    __shared__ __align__(16) uint32_t Ah[8 * 136];
    __shared__ __align__(16) uint32_t Al[8 * 136];
    __shared__ __align__(16) uint32_t Bpl[2][2][8 * 72];   // [stage][hi/lo]

    const int t    = threadIdx.x;
    const int wid  = t >> 5;
    const int lane = t & 31;
    const int g    = lane >> 2;        // 0..7
    const int tg   = lane & 3;         // 0..3
    const int wm   = (wid & 3) * 32;
    const int wn   = (wid >> 2) * 32;

    // ---- A raw staging mapping ----
    const int lrA  = t & 127;
    const int kcA8 = (t >> 7) * 8;     // 0 or 8
    const int growA = bm * 128 + lrA;
    const int bA = growA / d;
    const int mA = growA - bA * d;
    const float* xb = x + bA * FS + offl + mA;

    int fb = kcA8 / d;
    int ub = kcA8 - fb * d;
    const int q16 = 16 / d;
    const int r16 = 16 - q16 * d;

    // ---- B staging mapping: 16B per thread, both planes ----
    const int plB = t >> 7;                 // 0 = hi, 1 = lo
    const int k2B = (t >> 4) & 7;
    const int n4B = (t & 15) * 4;
    const uint32_t* Wsrc = (plB ? g_Wp_lo : g_Wp_hi)
                         + 2048 * offl + k2B * N + bn * 64 + n4B;

    const uint32_t araw_b = (uint32_t)__cvta_generic_to_shared(&Araw[0][0]);
    const uint32_t bpl_b  = (uint32_t)__cvta_generic_to_shared(&Bpl[0][0][0]);
    const uint32_t asA    = araw_b + (kcA8 * 128 + lrA) * 4;
    const uint32_t bsB    = bpl_b + ((plB * (8 * 72)) + k2B * 72 + n4B) * 4;
    const uint32_t ARAW_STAGE = 16 * 128 * 4;
    const uint32_t BPL_STAGE  = 2 * 8 * 72 * 4;

    float acc[2][4][4] = {};

    // ---- prologue: stage tile 0 ----
    {
        int f = fb, u = ub;
#pragma unroll
        for (int i = 0; i < 8; ++i) {
            cp4(asA + i * (128 * 4), xb + f * IR + u * d);
            if (++u == d) { u = 0; f++; }
        }
        cp16(bsB, Wsrc);
        cp_commit();
        fb += q16; ub += r16; if (ub >= d) { ub -= d; fb++; }
        Wsrc += 8 * N;
    }

    const int ntiles = K >> 4;
    for (int it = 0; it < ntiles; ++it) {
        const int s = it & 1;

        if (it + 1 < ntiles) {
            int f = fb, u = ub;
#pragma unroll
            for (int i = 0; i < 8; ++i) {
                cp4(asA + (s ^ 1) * ARAW_STAGE + i * (128 * 4), xb + f * IR + u * d);
                if (++u == d) { u = 0; f++; }
            }
            cp16(bsB + (s ^ 1) * BPL_STAGE, Wsrc);
            cp_commit();
            fb += q16; ub += r16; if (ub >= d) { ub -= d; fb++; }
            Wsrc += 8 * N;
            cp_wait<1>();
        } else {
            cp_wait<0>();
        }
        __syncthreads();

        // ---- convert raw A -> packed bf16x2 hi/lo planes ----
#pragma unroll
        for (int i = 0; i < 4; ++i) {
            const int idx = t + i * 256;        // 0..1023
            const int k2 = idx >> 7;
            const int m  = idx & 127;
            float e0 = Araw[s][(2 * k2) * 128 + m];
            float e1 = Araw[s][(2 * k2 + 1) * 128 + m];
            uint32_t lo;
            uint32_t hi = split_pack(e0, e1, lo);
            Ah[k2 * 136 + m] = hi;
            Al[k2 * 136 + m] = lo;
        }
        __syncthreads();

        // ---- fragments + MMA (one m16n8k16 step covers the 16-k tile) ----
        {
            uint32_t ah[2][4], al[2][4], bh[4][2], bl[4][2];
#pragma unroll
            for (int mi = 0; mi < 2; ++mi) {
                const int mb = wm + mi * 16 + g;
                ah[mi][0] = Ah[tg * 136 + mb];
                ah[mi][1] = Ah[tg * 136 + mb + 8];
                ah[mi][2] = Ah[(tg + 4) * 136 + mb];
                ah[mi][3] = Ah[(tg + 4) * 136 + mb + 8];
                al[mi][0] = Al[tg * 136 + mb];
                al[mi][1] = Al[tg * 136 + mb + 8];
                al[mi][2] = Al[(tg + 4) * 136 + mb];
                al[mi][3] = Al[(tg + 4) * 136 + mb + 8];
            }
            const uint32_t* Bh = Bpl[s][0];
            const uint32_t* Bl = Bpl[s][1];
#pragma unroll
            for (int ni = 0; ni < 4; ++ni) {
                const int nb = wn + ni * 8 + g;
                bh[ni][0] = Bh[tg * 72 + nb];
                bh[ni][1] = Bh[(tg + 4) * 72 + nb];
                bl[ni][0] = Bl[tg * 72 + nb];
                bl[ni][1] = Bl[(tg + 4) * 72 + nb];
            }
#pragma unroll
            for (int mi = 0; mi < 2; ++mi)
#pragma unroll
                for (int ni = 0; ni < 4; ++ni) {
                    mma_bf16(acc[mi][ni], ah[mi], bh[ni]);   // hi*hi
                    mma_bf16(acc[mi][ni], ah[mi], bl[ni]);   // hi*lo
                    mma_bf16(acc[mi][ni], al[mi], bh[ni]);   // lo*hi
                }
        }
        // next iteration's first __syncthreads orders MMA reads vs. convert writes
    }

    // ---- epilogue: scatter into out[b, g, off + v*d + m] ----
#pragma unroll
    for (int mi = 0; mi < 2; ++mi) {
#pragma unroll
        for (int cr = 0; cr < 2; ++cr) {
            const int row = bm * 128 + wm + mi * 16 + g + cr * 8;
            const int b = row / d;
            const int m = row - b * d;
            float* ob = out + b * FS + offl + m;
#pragma unroll
            for (int ni = 0; ni < 4; ++ni) {
#pragma unroll
                for (int cc = 0; cc < 2; ++cc) {
                    const int col = bn * 64 + wn + ni * 8 + tg * 2 + cc;
                    const int gg = col / d;
                    const int v  = col - gg * d;
                    ob[gg * IR + v * d] = acc[mi][ni][cr * 2 + cc];
                }
            }
        }
    }
}

// ---------------------------------------------------------------------------
extern "C" void kernel_launch(void* const* d_in, const int* in_sizes, int n_in,
                              void* d_out, int out_size)
{
    const float* x = nullptr;
    const float* D = nullptr;
    const float* w = nullptr;
    for (int i = 0; i < n_in; ++i) {
        if (in_sizes[i] == NROT * IR)         D = (const float*)d_in[i];
        else if (in_sizes[i] == F * F * NROT) w = (const float*)d_in[i];
        else                                  x = (const float*)d_in[i];
    }
    float* out = (float*)d_out;

    build_w_kernel<<<dim3(LMAX + 1, F), 256>>>(D, w);
    pack_w_kernel<<<dim3(1352, LMAX + 1), 256>>>();
    so3_bf16_kernel<<<3640, 256>>>(x, out);
}

// round 7
// speedup vs baseline: 2.7894x; 2.0355x over previous
#include <cuda_runtime.h>
#include <cstdint>

#define LMAX  6
#define BATCH 1024
#define F     64
#define IR    455
#define NROT  64
#define FS    (F * IR)   // 29120 floats per batch element

// Raw packed pre-scaled weights W_l[k, n] (f32), k=(f*d+u), n=(g*d+v).
__device__ float g_W[4096 * 455];
// Fragment-ordered bf16x2 hi/lo planes of W.
// Per l (offset 4096*off[l] u32): [ktile(4d)][bn(d)][plane(2)][wt(2)][c(2)][lane(32)][j(4)]
__device__ uint32_t g_Wf[4096 * 455];

// Tile decode tables, ordered l = 6..0 (largest K first).
__constant__ int c_cnt[7]  = {1352, 968, 648, 392, 200, 72, 8}; // 8*d*d
__constant__ int c_d[7]    = {13, 11, 9, 7, 5, 3, 1};
__constant__ int c_off[7]  = {286, 165, 84, 35, 10, 1, 0};

// ---------------------------------------------------------------------------
// helpers
// ---------------------------------------------------------------------------
__device__ __forceinline__ uint32_t pack_bf16x2(float lo_e, float hi_e) {
    uint32_t r;
    asm("cvt.rn.bf16x2.f32 %0, %1, %2;" : "=r"(r) : "f"(hi_e), "f"(lo_e));
    return r;
}
__device__ __forceinline__ float bf16_lo_f32(uint32_t p) { return __uint_as_float(p << 16); }
__device__ __forceinline__ float bf16_hi_f32(uint32_t p) { return __uint_as_float(p & 0xffff0000u); }

__device__ __forceinline__ uint32_t split_pack(float e0, float e1, uint32_t& lo_out) {
    uint32_t hi = pack_bf16x2(e0, e1);
    lo_out = pack_bf16x2(e0 - bf16_lo_f32(hi), e1 - bf16_hi_f32(hi));
    return hi;
}

__device__ __forceinline__ void mma_bf16(float c[4],
                                         const uint32_t a[4],
                                         const uint32_t b[2])
{
    asm volatile(
        "mma.sync.aligned.m16n8k16.row.col.f32.bf16.bf16.f32 "
        "{%0,%1,%2,%3}, {%4,%5,%6,%7}, {%8,%9}, {%0,%1,%2,%3};"
        : "+f"(c[0]), "+f"(c[1]), "+f"(c[2]), "+f"(c[3])
        : "r"(a[0]), "r"(a[1]), "r"(a[2]), "r"(a[3]), "r"(b[0]), "r"(b[1]));
}

__device__ __forceinline__ void cp4(uint32_t s, const float* g) {
    asm volatile("cp.async.ca.shared.global [%0], [%1], 4;" :: "r"(s), "l"(g));
}
__device__ __forceinline__ void cp16(uint32_t s, const void* g) {
    asm volatile("cp.async.cg.shared.global [%0], [%1], 16;" :: "r"(s), "l"(g));
}
__device__ __forceinline__ void cp_commit() {
    asm volatile("cp.async.commit_group;");
}
template <int W>
__device__ __forceinline__ void cp_wait() {
    asm volatile("cp.async.wait_group %0;" :: "n"(W));
}

// ---------------------------------------------------------------------------
// Kernel 1: psi GEMM.  C[fg, i] = sum_r w[fg, r] * D[r, i], scattered into g_W.
// grid = (8, 64): blockIdx.x = i-tile (64 cols), blockIdx.y = fg-tile (64 rows)
// ---------------------------------------------------------------------------
__global__ void __launch_bounds__(256) build_w2_kernel(const float* __restrict__ D,
                                                       const float* __restrict__ w)
{
    const int dtab[7] = {1, 3, 5, 7, 9, 11, 13};
    const int otab[7] = {0, 1, 10, 35, 84, 165, 286};

    __shared__ float Wsh[64][68];   // [r][fg_local]
    __shared__ float Dsh[64][68];   // [r][i_local]

    const int t   = threadIdx.x;
    const int fg0 = blockIdx.y * 64;
    const int i0  = blockIdx.x * 64;

    for (int idx = t; idx < 4096; idx += 256) {
        int row = idx >> 6, r = idx & 63;
        Wsh[r][row] = w[(fg0 + row) * 64 + r];
    }
    for (int idx = t; idx < 4096; idx += 256) {
        int r = idx >> 6, c = idx & 63;
        int i = i0 + c;
        Dsh[r][c] = (i < IR) ? D[r * IR + i] : 0.0f;
    }
    __syncthreads();

    const int ty = t >> 4, tx = t & 15;
    float acc[4][4] = {};

#pragma unroll 4
    for (int r = 0; r < 64; ++r) {
        float4 a4 = *(const float4*)&Wsh[r][ty * 4];
        float4 b4 = *(const float4*)&Dsh[r][tx * 4];
        float av[4] = {a4.x, a4.y, a4.z, a4.w};
        float bv[4] = {b4.x, b4.y, b4.z, b4.w};
#pragma unroll
        for (int i = 0; i < 4; ++i)
#pragma unroll
            for (int j = 0; j < 4; ++j)
                acc[i][j] += av[i] * bv[j];
    }

    // epilogue: scatter into g_W with per-l scale
#pragma unroll
    for (int j = 0; j < 4; ++j) {
        const int i = i0 + tx * 4 + j;
        if (i >= IR) continue;
        int l = 0;
#pragma unroll
        for (int q = 1; q < 7; ++q)
            if (i >= otab[q]) l = q;
        const int d = dtab[l], off = otab[l];
        const int jj = i - off;
        const int u = jj / d, v = jj - u * d;
        const float scale = rsqrtf((float)d) * (1.0f / 64.0f);
        const int base = 4096 * off;
        const int N = 64 * d;
#pragma unroll
        for (int i4 = 0; i4 < 4; ++i4) {
            const int fg = fg0 + ty * 4 + i4;
            const int f = fg >> 6, gg = fg & 63;
            g_W[base + (f * d + u) * N + gg * d + v] = scale * acc[i4][j];
        }
    }
}

// ---------------------------------------------------------------------------
// Kernel 1b: pack g_W into fragment-ordered bf16x2 hi/lo planes (g_Wf).
// grid = (2704, 7), guard idx < 4096*d*d.
// ---------------------------------------------------------------------------
__global__ void __launch_bounds__(256) pack_w2_kernel()
{
    const int dtab[7] = {1, 3, 5, 7, 9, 11, 13};
    const int otab[7] = {0, 1, 10, 35, 84, 165, 286};

    const int l = blockIdx.y;
    const int d = dtab[l];
    const int off = otab[l];
    const int N = 64 * d;
    const int tot = 4096 * d * d;
    const int idx = blockIdx.x * 256 + threadIdx.x;
    if (idx >= tot) return;

    const int j    = idx & 3;
    const int lane = (idx >> 2) & 31;
    const int c    = (idx >> 7) & 1;
    const int wt   = (idx >> 8) & 1;
    const int pl   = (idx >> 9) & 1;
    const int rest = idx >> 10;
    const int bn   = rest % d;
    const int kt   = rest / d;

    const int g  = lane >> 2;
    const int tg = lane & 3;
    const int k2 = kt * 8 + tg + 4 * (j & 1);
    const int n  = bn * 64 + wt * 32 + (2 * c + (j >> 1)) * 8 + g;

    const float e0 = g_W[4096 * off + (2 * k2) * N + n];
    const float e1 = g_W[4096 * off + (2 * k2 + 1) * N + n];
    uint32_t lo;
    uint32_t hi = split_pack(e0, e1, lo);
    g_Wf[4096 * off + idx] = pl ? lo : hi;
}

// ---------------------------------------------------------------------------
// Kernel 2: fused GEMM, bf16x2-split, fragment-ordered operands.
// Block tile 128x64, BK=16, 256 threads = 8 warps (4x2 of 32x32 warp tiles).
// ---------------------------------------------------------------------------
__global__ void __launch_bounds__(256) so3_v3_kernel(const float* __restrict__ x,
                                                     float* __restrict__ out)
{
    // ---- decode (l, bm, bn) ----
    int rem = blockIdx.x;
    int li = 0;
#pragma unroll
    for (int q = 0; q < 6; ++q)
        if (rem >= c_cnt[li]) { rem -= c_cnt[li]; li++; }
    const int d    = c_d[li];
    const int offl = c_off[li];
    const int bn   = rem % d;
    const int bm   = rem / d;

    const int K = 64 * d;

    __shared__ __align__(16) float    Araw[2][16][132];   // 16.9 KB
    __shared__ __align__(16) uint32_t AhF[1024];          // 4 KB, fragment order
    __shared__ __align__(16) uint32_t AlF[1024];          // 4 KB
    __shared__ __align__(16) uint32_t BF[2][1024];        // 8 KB, fragment order

    const int t    = threadIdx.x;
    const int wid  = t >> 5;
    const int lane = t & 31;
    const int g    = lane >> 2;
    const int tg   = lane & 3;
    const int wmi  = wid & 3;          // warp m-tile pair index (32-row tiles)
    const int wt   = wid >> 2;         // warp n half (32 cols)

    // ---- A raw staging mapping ----
    const int lrA  = t & 127;
    const int kcA8 = (t >> 7) * 8;
    const int growA = bm * 128 + lrA;
    const int bA = growA / d;
    const int mA = growA - bA * d;
    const float* xb = x + bA * FS + offl + mA;

    int fb = kcA8 / d;
    int ub = kcA8 - fb * d;
    const int q16 = 16 / d;
    const int r16 = 16 - q16 * d;

    // ---- B staging: one contiguous 4KB block per tile ----
    const uint32_t* Wsrc = g_Wf + 4096 * offl + bn * 1024 + t * 4;
    const int WstepB = d * 1024;   // u32 per k16 tile

    const uint32_t araw_b = (uint32_t)__cvta_generic_to_shared(&Araw[0][0][0]);
    const uint32_t bf_b   = (uint32_t)__cvta_generic_to_shared(&BF[0][0]);
    const uint32_t asA    = araw_b + (kcA8 * 132 + lrA) * 4;
    const uint32_t bsB    = bf_b + t * 16;
    const uint32_t ARAW_STAGE = 16 * 132 * 4;
    const uint32_t BF_STAGE   = 1024 * 4;

    float acc[2][4][4] = {};

    // ---- prologue ----
    {
        int f = fb, u = ub;
#pragma unroll
        for (int i = 0; i < 8; ++i) {
            cp4(asA + i * (132 * 4), xb + f * IR + u * d);
            if (++u == d) { u = 0; f++; }
        }
        cp16(bsB, Wsrc);
        cp_commit();
        fb += q16; ub += r16; if (ub >= d) { ub -= d; fb++; }
        Wsrc += WstepB;
    }

    const int ntiles = K >> 4;
    for (int it = 0; it < ntiles; ++it) {
        const int s = it & 1;

        if (it + 1 < ntiles) {
            int f = fb, u = ub;
#pragma unroll
            for (int i = 0; i < 8; ++i) {
                cp4(asA + (s ^ 1) * ARAW_STAGE + i * (132 * 4), xb + f * IR + u * d);
                if (++u == d) { u = 0; f++; }
            }
            cp16(bsB + (s ^ 1) * BF_STAGE, Wsrc);
            cp_commit();
            fb += q16; ub += r16; if (ub >= d) { ub -= d; fb++; }
            Wsrc += WstepB;
            cp_wait<1>();
        } else {
            cp_wait<0>();
        }
        __syncthreads();

        // ---- convert: raw f32 -> fragment-ordered bf16x2 hi/lo planes ----
        {
            const int m = (t >> 5) * 16 + g;
            float e00 = Araw[s][2 * tg    ][m];
            float e01 = Araw[s][2 * tg + 1][m];
            float e10 = Araw[s][2 * tg    ][m + 8];
            float e11 = Araw[s][2 * tg + 1][m + 8];
            float e20 = Araw[s][2 * tg + 8][m];
            float e21 = Araw[s][2 * tg + 9][m];
            float e30 = Araw[s][2 * tg + 8][m + 8];
            float e31 = Araw[s][2 * tg + 9][m + 8];
            uint32_t l0, l1, l2, l3;
            uint32_t h0 = split_pack(e00, e01, l0);
            uint32_t h1 = split_pack(e10, e11, l1);
            uint32_t h2 = split_pack(e20, e21, l2);
            uint32_t h3 = split_pack(e30, e31, l3);
            *(uint4*)&AhF[t * 4] = make_uint4(h0, h1, h2, h3);
            *(uint4*)&AlF[t * 4] = make_uint4(l0, l1, l2, l3);
        }
        __syncthreads();

        // ---- fragments (vectorized) + 24 MMA ----
        {
            uint32_t ah[2][4], al[2][4], bh[4][2], bl[4][2];
#pragma unroll
            for (int mi = 0; mi < 2; ++mi) {
                const int mt = wmi * 2 + mi;
                uint4 a4 = *(const uint4*)&AhF[(mt * 32 + lane) * 4];
                ah[mi][0] = a4.x; ah[mi][1] = a4.y; ah[mi][2] = a4.z; ah[mi][3] = a4.w;
                uint4 b4 = *(const uint4*)&AlF[(mt * 32 + lane) * 4];
                al[mi][0] = b4.x; al[mi][1] = b4.y; al[mi][2] = b4.z; al[mi][3] = b4.w;
            }
#pragma unroll
            for (int p = 0; p < 2; ++p) {
                uint32_t (*bf)[2] = p ? bl : bh;
                uint4 q0 = *(const uint4*)&BF[s][p * 512 + wt * 256 + lane * 4];
                uint4 q1 = *(const uint4*)&BF[s][p * 512 + wt * 256 + 128 + lane * 4];
                bf[0][0] = q0.x; bf[0][1] = q0.y; bf[1][0] = q0.z; bf[1][1] = q0.w;
                bf[2][0] = q1.x; bf[2][1] = q1.y; bf[3][0] = q1.z; bf[3][1] = q1.w;
            }
#pragma unroll
            for (int mi = 0; mi < 2; ++mi)
#pragma unroll
                for (int ni = 0; ni < 4; ++ni) {
                    mma_bf16(acc[mi][ni], ah[mi], bh[ni]);   // hi*hi
                    mma_bf16(acc[mi][ni], ah[mi], bl[ni]);   // hi*lo
                    mma_bf16(acc[mi][ni], al[mi], bh[ni]);   // lo*hi
                }
        }
        __syncthreads();
    }

    // ---- epilogue: scatter into out[b, g, off + v*d + m] ----
#pragma unroll
    for (int mi = 0; mi < 2; ++mi) {
#pragma unroll
        for (int cr = 0; cr < 2; ++cr) {
            const int row = bm * 128 + wmi * 32 + mi * 16 + g + cr * 8;
            const int b = row / d;
            const int m = row - b * d;
            float* ob = out + b * FS + offl + m;
#pragma unroll
            for (int ni = 0; ni < 4; ++ni) {
#pragma unroll
                for (int cc = 0; cc < 2; ++cc) {
                    const int col = bn * 64 + wt * 32 + ni * 8 + tg * 2 + cc;
                    const int gg = col / d;
                    const int v  = col - gg * d;
                    ob[gg * IR + v * d] = acc[mi][ni][cr * 2 + cc];
                }
            }
        }
    }
}

// ---------------------------------------------------------------------------
extern "C" void kernel_launch(void* const* d_in, const int* in_sizes, int n_in,
                              void* d_out, int out_size)
{
    const float* x = nullptr;
    const float* D = nullptr;
    const float* w = nullptr;
    for (int i = 0; i < n_in; ++i) {
        if (in_sizes[i] == NROT * IR)         D = (const float*)d_in[i];
        else if (in_sizes[i] == F * F * NROT) w = (const float*)d_in[i];
        else                                  x = (const float*)d_in[i];
    }
    float* out = (float*)d_out;

    build_w2_kernel<<<dim3(8, 64), 256>>>(D, w);
    pack_w2_kernel<<<dim3(2704, LMAX + 1), 256>>>();
    so3_v3_kernel<<<3640, 256>>>(x, out);
}

// round 9
// speedup vs baseline: 3.3275x; 1.1929x over previous
#include <cuda_runtime.h>
#include <cstdint>

#define LMAX  6
#define BATCH 1024
#define F     64
#define IR    455
#define NROT  64
#define FS    (F * IR)   // 29120 floats per batch element

// Raw packed pre-scaled weights W_l[k, n] (f32), k=(f*d+u), n=(g*d+v).
__device__ float g_W[4096 * 455];
// Fragment-ordered bf16x2 hi/lo planes of W.
// Per l (offset 4096*off[l] u32): [ktile(4d)][bn(d)][plane(2)][wt(2)][c(2)][lane(32)][j(4)]
__device__ uint32_t g_Wf[4096 * 455];

// Tile decode tables, ordered l = 6..0 (largest K first).
__constant__ int c_cnt[7]  = {1352, 968, 648, 392, 200, 72, 8}; // 8*d*d
__constant__ int c_d[7]    = {13, 11, 9, 7, 5, 3, 1};
__constant__ int c_off[7]  = {286, 165, 84, 35, 10, 1, 0};

// ---------------------------------------------------------------------------
// helpers
// ---------------------------------------------------------------------------
__device__ __forceinline__ uint32_t pack_bf16x2(float lo_e, float hi_e) {
    uint32_t r;
    asm("cvt.rn.bf16x2.f32 %0, %1, %2;" : "=r"(r) : "f"(hi_e), "f"(lo_e));
    return r;
}
__device__ __forceinline__ float bf16_lo_f32(uint32_t p) { return __uint_as_float(p << 16); }
__device__ __forceinline__ float bf16_hi_f32(uint32_t p) { return __uint_as_float(p & 0xffff0000u); }

__device__ __forceinline__ uint32_t split_pack(float e0, float e1, uint32_t& lo_out) {
    uint32_t hi = pack_bf16x2(e0, e1);
    lo_out = pack_bf16x2(e0 - bf16_lo_f32(hi), e1 - bf16_hi_f32(hi));
    return hi;
}

__device__ __forceinline__ void mma_bf16(float c[4],
                                         const uint32_t a[4],
                                         const uint32_t b[2])
{
    asm volatile(
        "mma.sync.aligned.m16n8k16.row.col.f32.bf16.bf16.f32 "
        "{%0,%1,%2,%3}, {%4,%5,%6,%7}, {%8,%9}, {%0,%1,%2,%3};"
        : "+f"(c[0]), "+f"(c[1]), "+f"(c[2]), "+f"(c[3])
        : "r"(a[0]), "r"(a[1]), "r"(a[2]), "r"(a[3]), "r"(b[0]), "r"(b[1]));
}

__device__ __forceinline__ void cp16(uint32_t s, const void* g) {
    asm volatile("cp.async.cg.shared.global [%0], [%1], 16;" :: "r"(s), "l"(g));
}
__device__ __forceinline__ void cp_commit() { asm volatile("cp.async.commit_group;"); }
template <int W>
__device__ __forceinline__ void cp_wait() { asm volatile("cp.async.wait_group %0;" :: "n"(W)); }

// ---------------------------------------------------------------------------
// Kernel 1: psi GEMM.  C[fg, i] = sum_r w[fg, r] * D[r, i], scattered into g_W.
// grid = (8, 64)
// ---------------------------------------------------------------------------
__global__ void __launch_bounds__(256) build_w2_kernel(const float* __restrict__ D,
                                                       const float* __restrict__ w)
{
    const int dtab[7] = {1, 3, 5, 7, 9, 11, 13};
    const int otab[7] = {0, 1, 10, 35, 84, 165, 286};

    __shared__ float Wsh[64][68];   // [r][fg_local]
    __shared__ float Dsh[64][68];   // [r][i_local]

    const int t   = threadIdx.x;
    const int fg0 = blockIdx.y * 64;
    const int i0  = blockIdx.x * 64;

    for (int idx = t; idx < 4096; idx += 256) {
        int row = idx >> 6, r = idx & 63;
        Wsh[r][row] = w[(fg0 + row) * 64 + r];
    }
    for (int idx = t; idx < 4096; idx += 256) {
        int r = idx >> 6, c = idx & 63;
        int i = i0 + c;
        Dsh[r][c] = (i < IR) ? D[r * IR + i] : 0.0f;
    }
    __syncthreads();

    const int ty = t >> 4, tx = t & 15;
    float acc[4][4] = {};

#pragma unroll 4
    for (int r = 0; r < 64; ++r) {
        float4 a4 = *(const float4*)&Wsh[r][ty * 4];
        float4 b4 = *(const float4*)&Dsh[r][tx * 4];
        float av[4] = {a4.x, a4.y, a4.z, a4.w};
        float bv[4] = {b4.x, b4.y, b4.z, b4.w};
#pragma unroll
        for (int i = 0; i < 4; ++i)
#pragma unroll
            for (int j = 0; j < 4; ++j)
                acc[i][j] += av[i] * bv[j];
    }

#pragma unroll
    for (int j = 0; j < 4; ++j) {
        const int i = i0 + tx * 4 + j;
        if (i >= IR) continue;
        int l = 0;
#pragma unroll
        for (int q = 1; q < 7; ++q)
            if (i >= otab[q]) l = q;
        const int d = dtab[l], off = otab[l];
        const int jj = i - off;
        const int u = jj / d, v = jj - u * d;
        const float scale = rsqrtf((float)d) * (1.0f / 64.0f);
        const int base = 4096 * off;
        const int N = 64 * d;
#pragma unroll
        for (int i4 = 0; i4 < 4; ++i4) {
            const int fg = fg0 + ty * 4 + i4;
            const int f = fg >> 6, gg = fg & 63;
            g_W[base + (f * d + u) * N + gg * d + v] = scale * acc[i4][j];
        }
    }
}

// ---------------------------------------------------------------------------
// Kernel 1b: pack g_W into fragment-ordered bf16x2 hi/lo planes (g_Wf).
// grid = (2704, 7), guard idx < 4096*d*d.
// ---------------------------------------------------------------------------
__global__ void __launch_bounds__(256) pack_w2_kernel()
{
    const int dtab[7] = {1, 3, 5, 7, 9, 11, 13};
    const int otab[7] = {0, 1, 10, 35, 84, 165, 286};

    const int l = blockIdx.y;
    const int d = dtab[l];
    const int off = otab[l];
    const int N = 64 * d;
    const int tot = 4096 * d * d;
    const int idx = blockIdx.x * 256 + threadIdx.x;
    if (idx >= tot) return;

    const int j    = idx & 3;
    const int lane = (idx >> 2) & 31;
    const int c    = (idx >> 7) & 1;
    const int wt   = (idx >> 8) & 1;
    const int pl   = (idx >> 9) & 1;
    const int rest = idx >> 10;
    const int bn   = rest % d;
    const int kt   = rest / d;

    const int g  = lane >> 2;
    const int tg = lane & 3;
    const int k2 = kt * 8 + tg + 4 * (j & 1);
    const int n  = bn * 64 + wt * 32 + (2 * c + (j >> 1)) * 8 + g;

    const float e0 = g_W[4096 * off + (2 * k2) * N + n];
    const float e1 = g_W[4096 * off + (2 * k2 + 1) * N + n];
    uint32_t lo;
    uint32_t hi = split_pack(e0, e1, lo);
    g_Wf[4096 * off + idx] = pl ? lo : hi;
}

// ---------------------------------------------------------------------------
// Kernel 2: fused GEMM, bf16x2-split, fragment-ordered operands,
// direct-LDG A staging, double-buffered smem, ONE __syncthreads per k16 tile.
// Block tile 128x64, 256 threads = 8 warps (4x2 of 32x32 warp tiles).
// ---------------------------------------------------------------------------
__global__ void __launch_bounds__(256) so3_v4_kernel(const float* __restrict__ x,
                                                     float* __restrict__ out)
{
    // ---- decode (l, bm, bn) ----
    int rem = blockIdx.x;
    int li = 0;
#pragma unroll
    for (int q = 0; q < 6; ++q)
        if (rem >= c_cnt[li]) { rem -= c_cnt[li]; li++; }
    const int d    = c_d[li];
    const int offl = c_off[li];
    const int bn   = rem % d;
    const int bm   = rem / d;

    const int K = 64 * d;

    __shared__ __align__(16) uint32_t AhF[2][1024];   // fragment order, double buffered
    __shared__ __align__(16) uint32_t AlF[2][1024];
    __shared__ __align__(16) uint32_t BF[2][1024];

    const int t    = threadIdx.x;
    const int wid  = t >> 5;
    const int lane = t & 31;
    const int g    = lane >> 2;
    const int tg   = lane & 3;
    const int wmi  = wid & 3;          // warp m index (32-row tiles)
    const int wt   = wid >> 2;         // warp n half (32 cols)

    // ---- direct A gather mapping: this thread's fragment slot ----
    // rows m, m+8 ; k-locals 2tg, 2tg+1, 2tg+8, 2tg+9
    const int m    = (t >> 5) * 16 + g;
    const int gr0  = bm * 128 + m;
    const int gr8  = gr0 + 8;
    const int b0_  = gr0 / d;
    const int b8_  = gr8 / d;
    const float* base0 = x + b0_ * FS + offl + (gr0 - b0_ * d);
    const float* base8 = x + b8_ * FS + offl + (gr8 - b8_ * d);

    const int q16 = 16 / d;
    const int r16 = 16 - q16 * d;
    const int kl[4] = {2 * tg, 2 * tg + 1, 2 * tg + 8, 2 * tg + 9};
    int uA[4], offA[4];
#pragma unroll
    for (int j = 0; j < 4; ++j) {
        const int f = kl[j] / d;
        uA[j]   = kl[j] - f * d;
        offA[j] = f * IR + uA[j] * d;
    }

    // ---- B staging: one contiguous 4KB block per tile ----
    const uint32_t* Wsrc = g_Wf + 4096 * offl + bn * 1024 + t * 4;
    const int WstepB = d * 1024;   // u32 per k16 tile

    const uint32_t bf_b = (uint32_t)__cvta_generic_to_shared(&BF[0][0]);
    const uint32_t bsB  = bf_b + t * 16;
    const uint32_t BF_STAGE = 1024 * 4;

    float acc[2][4][4] = {};
    float v[8];

    // ---- prologue: LDG A(0), cp.async B(0) ----
    {
        v[0] = base0[offA[0]]; v[1] = base0[offA[1]];
        v[2] = base8[offA[0]]; v[3] = base8[offA[1]];
        v[4] = base0[offA[2]]; v[5] = base0[offA[3]];
        v[6] = base8[offA[2]]; v[7] = base8[offA[3]];
#pragma unroll
        for (int j = 0; j < 4; ++j) {
            uA[j] += r16; offA[j] += q16 * IR + r16 * d;
            if (uA[j] >= d) { uA[j] -= d; offA[j] += IR - d * d; }
        }
        cp16(bsB, Wsrc);
        cp_commit();
        Wsrc += WstepB;
    }

    const int ntiles = K >> 4;
    for (int it = 0; it < ntiles; ++it) {
        const int s = it & 1;

        // ---- 1. split + STS current A into buffer s ----
        {
            uint32_t l0, l1, l2, l3;
            uint32_t h0 = split_pack(v[0], v[1], l0);
            uint32_t h1 = split_pack(v[2], v[3], l1);
            uint32_t h2 = split_pack(v[4], v[5], l2);
            uint32_t h3 = split_pack(v[6], v[7], l3);
            *(uint4*)&AhF[s][t * 4] = make_uint4(h0, h1, h2, h3);
            *(uint4*)&AlF[s][t * 4] = make_uint4(l0, l1, l2, l3);
        }

        // ---- 2. prefetch A(it+1) ----
        if (it + 1 < ntiles) {
            v[0] = base0[offA[0]]; v[1] = base0[offA[1]];
            v[2] = base8[offA[0]]; v[3] = base8[offA[1]];
            v[4] = base0[offA[2]]; v[5] = base0[offA[3]];
            v[6] = base8[offA[2]]; v[7] = base8[offA[3]];
#pragma unroll
            for (int j = 0; j < 4; ++j) {
                uA[j] += r16; offA[j] += q16 * IR + r16 * d;
                if (uA[j] >= d) { uA[j] -= d; offA[j] += IR - d * d; }
            }
        }

        // ---- 3. wait B(it), barrier ----
        cp_wait<0>();
        __syncthreads();

        // ---- 4. issue B(it+1) into buffer s^1 ----
        if (it + 1 < ntiles) {
            cp16(bsB + (s ^ 1) * BF_STAGE, Wsrc);
            cp_commit();
            Wsrc += WstepB;
        }

        // ---- 5. fragments + 24 MMA on buffer s ----
        {
            uint32_t ah[2][4], al[2][4], bh[4][2], bl[4][2];
#pragma unroll
            for (int mi = 0; mi < 2; ++mi) {
                const int mt = wmi * 2 + mi;
                uint4 a4 = *(const uint4*)&AhF[s][(mt * 32 + lane) * 4];
                ah[mi][0] = a4.x; ah[mi][1] = a4.y; ah[mi][2] = a4.z; ah[mi][3] = a4.w;
                uint4 b4 = *(const uint4*)&AlF[s][(mt * 32 + lane) * 4];
                al[mi][0] = b4.x; al[mi][1] = b4.y; al[mi][2] = b4.z; al[mi][3] = b4.w;
            }
#pragma unroll
            for (int p = 0; p < 2; ++p) {
                uint32_t (*bf)[2] = p ? bl : bh;
                uint4 q0 = *(const uint4*)&BF[s][p * 512 + wt * 256 + lane * 4];
                uint4 q1 = *(const uint4*)&BF[s][p * 512 + wt * 256 + 128 + lane * 4];
                bf[0][0] = q0.x; bf[0][1] = q0.y; bf[1][0] = q0.z; bf[1][1] = q0.w;
                bf[2][0] = q1.x; bf[2][1] = q1.y; bf[3][0] = q1.z; bf[3][1] = q1.w;
            }
#pragma unroll
            for (int mi = 0; mi < 2; ++mi)
#pragma unroll
                for (int ni = 0; ni < 4; ++ni) {
                    mma_bf16(acc[mi][ni], ah[mi], bh[ni]);   // hi*hi
                    mma_bf16(acc[mi][ni], ah[mi], bl[ni]);   // hi*lo
                    mma_bf16(acc[mi][ni], al[mi], bh[ni]);   // lo*hi
                }
        }
        // no trailing barrier: next iteration writes buffer s^1, reads of s are done
        // before the next __syncthreads, which orders them against the following
        // overwrite of s (two iterations later).
    }

    // ---- epilogue: scatter into out[b, g, off + v*d + m] ----
#pragma unroll
    for (int mi = 0; mi < 2; ++mi) {
#pragma unroll
        for (int cr = 0; cr < 2; ++cr) {
            const int row = bm * 128 + wmi * 32 + mi * 16 + g + cr * 8;
            const int b = row / d;
            const int mm = row - b * d;
            float* ob = out + b * FS + offl + mm;
#pragma unroll
            for (int ni = 0; ni < 4; ++ni) {
#pragma unroll
                for (int cc = 0; cc < 2; ++cc) {
                    const int col = bn * 64 + wt * 32 + ni * 8 + tg * 2 + cc;
                    const int gg = col / d;
                    const int vv = col - gg * d;
                    ob[gg * IR + vv * d] = acc[mi][ni][cr * 2 + cc];
                }
            }
        }
    }
}

// ---------------------------------------------------------------------------
extern "C" void kernel_launch(void* const* d_in, const int* in_sizes, int n_in,
                              void* d_out, int out_size)
{
    const float* x = nullptr;
    const float* D = nullptr;
    const float* w = nullptr;
    for (int i = 0; i < n_in; ++i) {
        if (in_sizes[i] == NROT * IR)         D = (const float*)d_in[i];
        else if (in_sizes[i] == F * F * NROT) w = (const float*)d_in[i];
        else                                  x = (const float*)d_in[i];
    }
    float* out = (float*)d_out;

    build_w2_kernel<<<dim3(8, 64), 256>>>(D, w);
    pack_w2_kernel<<<dim3(2704, LMAX + 1), 256>>>();
    so3_v4_kernel<<<3640, 256>>>(x, out);
}